// round 7
// baseline (speedup 1.0000x reference)
#include <cuda_runtime.h>
#include <math.h>

#define NN 100000
#define DD 256
#define ND4 (DD / 4)
#define EE 3200000
#define SCAN_BLKS 400

// Scratch (static device globals)
__device__ float  g_dis[NN];
__device__ int    g_deg[NN];
__device__ int    g_rowptr[NN + 1];
__device__ int    g_cursor[NN];
__device__ int    g_nbr[EE];
__device__ int    g_bsum[SCAN_BLKS];
__device__ int    g_boff[SCAN_BLKS];
__device__ float4 g_y[(size_t)NN * ND4];
__device__ float4 g_h[(size_t)NN * ND4];
__device__ int    g_is32;

// ---------------- dtype probe ----------------

__global__ void k_probe(const int* __restrict__ ei_raw) {
    __shared__ int any;
    if (threadIdx.x == 0) any = 0;
    __syncthreads();
    if (ei_raw[threadIdx.x * 2 + 1] != 0) atomicOr(&any, 1);
    __syncthreads();
    if (threadIdx.x == 0) g_is32 = any;
}

__device__ __forceinline__ int edge_id(const void* p, size_t idx) {
    return g_is32 ? ((const int*)p)[idx] : (int)((const long long*)p)[idx];
}

// ---------------- degree / CSR build ----------------

__global__ void k_deg_zero(int n) {
    int i = blockIdx.x * blockDim.x + threadIdx.x;
    if (i < n) g_deg[i] = 0;
}

__global__ void k_deg_accum(const void* __restrict__ ei, int e) {
    int i = blockIdx.x * blockDim.x + threadIdx.x;
    if (i < e) atomicAdd(&g_deg[edge_id(ei, (size_t)e + i)], 1);
}

__global__ void k_scan_part(int n) {
    const int tid = threadIdx.x;
    int i = blockIdx.x * 256 + tid;
    int v = (i < n) ? g_deg[i] : 0;
#pragma unroll
    for (int off = 16; off > 0; off >>= 1)
        v += __shfl_down_sync(0xffffffffu, v, off);
    __shared__ int ws[8];
    if ((tid & 31) == 0) ws[tid >> 5] = v;
    __syncthreads();
    if (tid == 0) {
        int s = 0;
#pragma unroll
        for (int w = 0; w < 8; w++) s += ws[w];
        g_bsum[blockIdx.x] = s;
    }
}

__global__ void k_scan_mid(int n) {
    __shared__ int sm[512];
    const int t = threadIdx.x;
    sm[t] = (t < SCAN_BLKS) ? g_bsum[t] : 0;
    __syncthreads();
    for (int off = 1; off < 512; off <<= 1) {
        int v = (t >= off) ? sm[t - off] : 0;
        __syncthreads();
        sm[t] += v;
        __syncthreads();
    }
    if (t < SCAN_BLKS) g_boff[t] = (t > 0) ? sm[t - 1] : 0;
    if (t == 511) g_rowptr[n] = sm[511];
}

// Phase 3 + dis: rowptr/cursor/dis in one pass
__global__ void k_scan_out(int n) {
    const int tid  = threadIdx.x;
    const int lane = tid & 31;
    const int wid  = tid >> 5;
    int i = blockIdx.x * 256 + tid;
    int v = (i < n) ? g_deg[i] : 0;

    int incl = v;
#pragma unroll
    for (int off = 1; off < 32; off <<= 1) {
        int u = __shfl_up_sync(0xffffffffu, incl, off);
        if (lane >= off) incl += u;
    }
    __shared__ int ws[8];
    if (lane == 31) ws[wid] = incl;
    __syncthreads();
    int warpoff = 0;
#pragma unroll
    for (int w = 0; w < 8; w++)
        if (w < wid) warpoff += ws[w];

    int excl = g_boff[blockIdx.x] + warpoff + incl - v;
    if (i < n) {
        g_rowptr[i] = excl;
        g_cursor[i] = excl;
        g_dis[i]    = rsqrtf((float)(v + 1));
    }
}

__global__ void k_fill(const void* __restrict__ ei, int e) {
    int i = blockIdx.x * blockDim.x + threadIdx.x;
    if (i >= e) return;
    int s = edge_id(ei, i);
    int d = edge_id(ei, (size_t)e + i);
    int pos = atomicAdd(&g_cursor[d], 1);
    g_nbr[pos] = s;
}

// ---------------- tf32 helpers ----------------

__device__ __forceinline__ unsigned f2tf(float x) {
    unsigned r;
    asm("cvt.rna.tf32.f32 %0, %1;" : "=r"(r) : "f"(x));
    return r;
}

__device__ __forceinline__ void mma8(float acc[4], const unsigned a[4], const unsigned b[2]) {
    asm volatile(
        "mma.sync.aligned.m16n8k8.row.col.f32.tf32.tf32.f32 "
        "{%0,%1,%2,%3},{%4,%5,%6,%7},{%8,%9},{%0,%1,%2,%3};"
        : "+f"(acc[0]), "+f"(acc[1]), "+f"(acc[2]), "+f"(acc[3])
        : "r"(a[0]), "r"(a[1]), "r"(a[2]), "r"(a[3]), "r"(b[0]), "r"(b[1]));
}

// ---------------- GEMM: Y = A @ W  (tensor core, tf32 3-term split; no dis) ----

#define APAD 20
#define BPAD 136
#define ABUF (128 * APAD)
#define BBUF (16 * BPAD)
#define SM_FLOATS (2 * ABUF * 2 + 2 * BBUF * 2)

__global__ void __launch_bounds__(256)
k_gemm_tc(const float* __restrict__ A, const float* __restrict__ W, int n) {
    extern __shared__ float sm[];
    float* sAh = sm;
    float* sAl = sAh + 2 * ABUF;
    float* sBh = sAl + 2 * ABUF;
    float* sBl = sBh + 2 * BBUF;

    const int tid  = threadIdx.x;
    const int lane = tid & 31;
    const int warp = tid >> 5;
    const int wm = (warp & 1) * 64;
    const int wn = (warp >> 1) * 32;
    const int qr = lane >> 2;
    const int qc = lane & 3;
    const int rowBase = blockIdx.y * 128;
    const int colBase = blockIdx.x * 128;

    const int ar  = tid >> 2;
    const int ak4 = (tid & 3) * 4;
    const int bkr = tid >> 5;
    const int bc4 = (tid & 31) * 4;

    float acc[4][4][4] = {};
    float4 aR[2], bR[2];

#define LOAD_G(kbase)                                                              \
    {                                                                              \
        _Pragma("unroll")                                                          \
        for (int i = 0; i < 2; i++) {                                              \
            int grow = rowBase + ar + i * 64;                                      \
            aR[i] = make_float4(0.f, 0.f, 0.f, 0.f);                               \
            if (grow < n)                                                          \
                aR[i] = *(const float4*)(A + (size_t)grow * DD + (kbase) + ak4);   \
            bR[i] = *(const float4*)(W + (size_t)((kbase) + bkr + i * 8) * DD      \
                                        + colBase + bc4);                          \
        }                                                                          \
    }

#define STORE_S(buf)                                                               \
    {                                                                              \
        _Pragma("unroll")                                                          \
        for (int i = 0; i < 2; i++) {                                              \
            int abase = (buf) * ABUF + (ar + i * 64) * APAD + ak4;                 \
            const float* av = (const float*)&aR[i];                                \
            _Pragma("unroll")                                                      \
            for (int j = 0; j < 4; j++) {                                          \
                unsigned h = f2tf(av[j]);                                          \
                float hf = __uint_as_float(h);                                     \
                sAh[abase + j] = hf;                                               \
                sAl[abase + j] = __uint_as_float(f2tf(av[j] - hf));                \
            }                                                                      \
            int bbase = (buf) * BBUF + (bkr + i * 8) * BPAD + bc4;                 \
            const float* bv = (const float*)&bR[i];                                \
            _Pragma("unroll")                                                      \
            for (int j = 0; j < 4; j++) {                                          \
                unsigned h = f2tf(bv[j]);                                          \
                float hf = __uint_as_float(h);                                     \
                sBh[bbase + j] = hf;                                               \
                sBl[bbase + j] = __uint_as_float(f2tf(bv[j] - hf));                \
            }                                                                      \
        }                                                                          \
    }

    LOAD_G(0)
    STORE_S(0)
    __syncthreads();

    const int NSTAGE = DD / 16;
    for (int s = 0; s < NSTAGE; s++) {
        int buf = s & 1;
        if (s + 1 < NSTAGE) LOAD_G((s + 1) * 16)

#pragma unroll
        for (int kk = 0; kk < 16; kk += 8) {
            unsigned bh[4][2], bl[4][2];
#pragma unroll
            for (int nt = 0; nt < 4; nt++) {
                int nn = wn + nt * 8 + qr;
                int b0 = buf * BBUF + (kk + qc) * BPAD + nn;
                int b1 = buf * BBUF + (kk + qc + 4) * BPAD + nn;
                bh[nt][0] = __float_as_uint(sBh[b0]);
                bh[nt][1] = __float_as_uint(sBh[b1]);
                bl[nt][0] = __float_as_uint(sBl[b0]);
                bl[nt][1] = __float_as_uint(sBl[b1]);
            }
#pragma unroll
            for (int mt = 0; mt < 4; mt++) {
                int r0 = buf * ABUF + (wm + mt * 16 + qr) * APAD + kk + qc;
                int r1 = r0 + 8 * APAD;
                unsigned ah[4], al[4];
                ah[0] = __float_as_uint(sAh[r0]);
                ah[1] = __float_as_uint(sAh[r1]);
                ah[2] = __float_as_uint(sAh[r0 + 4]);
                ah[3] = __float_as_uint(sAh[r1 + 4]);
                al[0] = __float_as_uint(sAl[r0]);
                al[1] = __float_as_uint(sAl[r1]);
                al[2] = __float_as_uint(sAl[r0 + 4]);
                al[3] = __float_as_uint(sAl[r1 + 4]);
#pragma unroll
                for (int nt = 0; nt < 4; nt++) {
                    mma8(acc[mt][nt], ah, bh[nt]);
                    mma8(acc[mt][nt], ah, bl[nt]);
                    mma8(acc[mt][nt], al, bh[nt]);
                }
            }
        }

        if (s + 1 < NSTAGE) {
            STORE_S(buf ^ 1)
            __syncthreads();
        }
    }

    float* gy = (float*)g_y;
#pragma unroll
    for (int mt = 0; mt < 4; mt++) {
        int m0 = rowBase + wm + mt * 16 + qr;
        int m1 = m0 + 8;
#pragma unroll
        for (int nt = 0; nt < 4; nt++) {
            int n0 = colBase + wn + nt * 8 + qc * 2;
            if (m0 < n) {
                float2 v = make_float2(acc[mt][nt][0], acc[mt][nt][1]);
                *(float2*)(gy + (size_t)m0 * DD + n0) = v;
            }
            if (m1 < n) {
                float2 v = make_float2(acc[mt][nt][2], acc[mt][nt][3]);
                *(float2*)(gy + (size_t)m1 * DD + n0) = v;
            }
        }
    }
}

// ---------------- pull + epilogue: H[v] = elu(dis[v]*(dis[v]*y[v] + sum dis[s]*y[s]) + b) ----

__device__ __forceinline__ float elu1(float x) {
    return x > 0.f ? x : (expf(x) - 1.0f);
}

__global__ void __launch_bounds__(256)
k_pull(const float4* __restrict__ b, float4* __restrict__ H, int n) {
    const int warp = (blockIdx.x * blockDim.x + threadIdx.x) >> 5;
    const int lane = threadIdx.x & 31;
    if (warp >= n) return;
    const int node = warp;

    const float s = g_dis[node];
    const float4* yrow = g_y + (size_t)node * ND4;
    float4 y0 = yrow[lane];
    float4 y1 = yrow[lane + 32];
    float4 acc0 = make_float4(y0.x * s, y0.y * s, y0.z * s, y0.w * s);
    float4 acc1 = make_float4(y1.x * s, y1.y * s, y1.z * s, y1.w * s);

    int j   = g_rowptr[node];
    int end = g_rowptr[node + 1];

    for (; j + 1 < end; j += 2) {
        int s0 = g_nbr[j];
        int s1 = g_nbr[j + 1];
        float d0 = g_dis[s0];
        float d1 = g_dis[s1];
        const float4* p0 = g_y + (size_t)s0 * ND4;
        const float4* p1 = g_y + (size_t)s1 * ND4;
        float4 u0 = p0[lane];
        float4 u1 = p0[lane + 32];
        float4 v0 = p1[lane];
        float4 v1 = p1[lane + 32];
        acc0.x = fmaf(u0.x, d0, acc0.x); acc0.y = fmaf(u0.y, d0, acc0.y);
        acc0.z = fmaf(u0.z, d0, acc0.z); acc0.w = fmaf(u0.w, d0, acc0.w);
        acc1.x = fmaf(u1.x, d0, acc1.x); acc1.y = fmaf(u1.y, d0, acc1.y);
        acc1.z = fmaf(u1.z, d0, acc1.z); acc1.w = fmaf(u1.w, d0, acc1.w);
        acc0.x = fmaf(v0.x, d1, acc0.x); acc0.y = fmaf(v0.y, d1, acc0.y);
        acc0.z = fmaf(v0.z, d1, acc0.z); acc0.w = fmaf(v0.w, d1, acc0.w);
        acc1.x = fmaf(v1.x, d1, acc1.x); acc1.y = fmaf(v1.y, d1, acc1.y);
        acc1.z = fmaf(v1.z, d1, acc1.z); acc1.w = fmaf(v1.w, d1, acc1.w);
    }
    if (j < end) {
        int s0 = g_nbr[j];
        float d0 = g_dis[s0];
        const float4* p0 = g_y + (size_t)s0 * ND4;
        float4 u0 = p0[lane];
        float4 u1 = p0[lane + 32];
        acc0.x = fmaf(u0.x, d0, acc0.x); acc0.y = fmaf(u0.y, d0, acc0.y);
        acc0.z = fmaf(u0.z, d0, acc0.z); acc0.w = fmaf(u0.w, d0, acc0.w);
        acc1.x = fmaf(u1.x, d0, acc1.x); acc1.y = fmaf(u1.y, d0, acc1.y);
        acc1.z = fmaf(u1.z, d0, acc1.z); acc1.w = fmaf(u1.w, d0, acc1.w);
    }

    float4 b0 = b[lane];
    float4 b1 = b[lane + 32];
    float4 o0, o1;
    o0.x = elu1(fmaf(acc0.x, s, b0.x));
    o0.y = elu1(fmaf(acc0.y, s, b0.y));
    o0.z = elu1(fmaf(acc0.z, s, b0.z));
    o0.w = elu1(fmaf(acc0.w, s, b0.w));
    o1.x = elu1(fmaf(acc1.x, s, b1.x));
    o1.y = elu1(fmaf(acc1.y, s, b1.y));
    o1.z = elu1(fmaf(acc1.z, s, b1.z));
    o1.w = elu1(fmaf(acc1.w, s, b1.w));
    H[(size_t)node * ND4 + lane]      = o0;
    H[(size_t)node * ND4 + lane + 32] = o1;
}

// ---------------- launch ----------------

extern "C" void kernel_launch(void* const* d_in, const int* in_sizes, int n_in,
                              void* d_out, int out_size) {
    const float* x  = (const float*)d_in[0];
    const void*  ei = d_in[1];
    const float* W1 = (const float*)d_in[2];
    const float* b1 = (const float*)d_in[3];
    const float* W2 = (const float*)d_in[4];
    const float* b2 = (const float*)d_in[5];
    float4* out = (float4*)d_out;

    int n = in_sizes[0] / DD;        // 100000
    int e = in_sizes[1] / 2;         // 3200000

    void* p_h = nullptr;
    cudaGetSymbolAddress(&p_h, g_h);
    float4* hbuf = (float4*)p_h;

    const size_t smBytes = (size_t)SM_FLOATS * sizeof(float);
    cudaFuncSetAttribute(k_gemm_tc, cudaFuncAttributeMaxDynamicSharedMemorySize,
                         (int)smBytes);

    // Side stream + fork/join events (created once; host resources only).
    static cudaStream_t s1 = nullptr;
    static cudaEvent_t  eFork = nullptr, eJoin = nullptr;
    if (s1 == nullptr) {
        cudaStreamCreateWithFlags(&s1, cudaStreamNonBlocking);
        cudaEventCreateWithFlags(&eFork, cudaEventDisableTiming);
        cudaEventCreateWithFlags(&eJoin, cudaEventDisableTiming);
    }

    dim3 gGrid(DD / 128, (n + 127) / 128);
    int pGrid = (n + 7) / 8;

    // Fork: CSR build on s1 concurrently with GEMM-1 on the main stream.
    cudaEventRecord(eFork, 0);
    cudaStreamWaitEvent(s1, eFork, 0);

    k_probe    <<<1, 512, 0, s1>>>((const int*)ei);
    k_deg_zero <<<(n + 255) / 256, 256, 0, s1>>>(n);
    k_deg_accum<<<(e + 255) / 256, 256, 0, s1>>>(ei, e);
    k_scan_part<<<SCAN_BLKS, 256, 0, s1>>>(n);
    k_scan_mid <<<1, 512, 0, s1>>>(n);
    k_scan_out <<<SCAN_BLKS, 256, 0, s1>>>(n);
    k_fill     <<<(e + 255) / 256, 256, 0, s1>>>(ei, e);
    cudaEventRecord(eJoin, s1);

    // GEMM-1 no longer depends on dis — runs concurrently with CSR build.
    k_gemm_tc<<<gGrid, 256, smBytes>>>(x, W1, n);

    // Join before pull-1 (needs CSR + dis + y).
    cudaStreamWaitEvent(0, eJoin, 0);
    k_pull   <<<pGrid, 256>>>((const float4*)b1, hbuf, n);

    // layer 2: g_h -> out
    k_gemm_tc<<<gGrid, 256, smBytes>>>((const float*)hbuf, W2, n);
    k_pull   <<<pGrid, 256>>>((const float4*)b2, out, n);
}